// round 9
// baseline (speedup 1.0000x reference)
#include <cuda_runtime.h>

// SinkhornScorer fused kernel for GB300 (sm_103a).
// R9: warp-per-batch (R8 design) + FIX: v-phase dustbin-row term seeded only
// on rg==0 lanes so the rg-reduction counts it exactly once (was 8x).
//  - GEMM: thread tile 8 rows x 16 cols, acc as packed f32x2 col pairs;
//    x scalar-broadcast from swizzled smem, y k-major (transposed at staging).
//  - K = exp(C) in registers; Sinkhorn fully warp-local, zero CTA barriers.
//  - matching recomputes C = __logf(K); dustbins/corner special-cased.

namespace {
constexpr int NP = 65;
constexpr float LOG128 = 4.852030263919617f;
constexpr float MU_IN  = 0.0078125f;   // 1/128
constexpr float MU_DB  = 0.5f;         // 64/128

__device__ __forceinline__ float warp_sum(float v) {
#pragma unroll
    for (int o = 16; o; o >>= 1) v += __shfl_xor_sync(0xffffffffu, v, o);
    return v;
}
__device__ __forceinline__ unsigned long long ffma2(
    unsigned long long a, unsigned long long b, unsigned long long c) {
    unsigned long long d;
    asm("fma.rn.f32x2 %0, %1, %2, %3;" : "=l"(d) : "l"(a), "l"(b), "l"(c));
    return d;
}
__device__ __forceinline__ unsigned long long fmul2(
    unsigned long long a, unsigned long long b) {
    unsigned long long d;
    asm("mul.rn.f32x2 %0, %1, %2;" : "=l"(d) : "l"(a), "l"(b));
    return d;
}
__device__ __forceinline__ unsigned long long fadd2(
    unsigned long long a, unsigned long long b) {
    unsigned long long d;
    asm("add.rn.f32x2 %0, %1, %2;" : "=l"(d) : "l"(a), "l"(b));
    return d;
}
__device__ __forceinline__ unsigned long long pack2(float lo, float hi) {
    unsigned long long d;
    asm("mov.b64 %0, {%1, %2};" : "=l"(d) : "f"(lo), "f"(hi));
    return d;
}
__device__ __forceinline__ void unpack2(unsigned long long v, float& lo, float& hi) {
    asm("mov.b64 {%0, %1}, %2;" : "=f"(lo), "=f"(hi) : "l"(v));
}
__device__ __forceinline__ float pairsum(unsigned long long v) {
    float lo, hi; unpack2(v, lo, hi); return lo + hi;
}
}  // namespace

__global__ void __launch_bounds__(256) sinkhorn_fused_kernel(
    const float* __restrict__ x, const float* __restrict__ y,
    const float* __restrict__ gamma, const float* __restrict__ beta,
    const float* __restrict__ wdb, const float* __restrict__ bdb,
    float* __restrict__ out_match, float* __restrict__ out_score,
    int write_score)
{
    const int t    = threadIdx.x;
    const int lane = t & 31;
    const int w    = t >> 5;
    const int rg   = lane >> 2;    // row group: rows rg*8 .. rg*8+7
    const int cg   = lane & 3;     // col group: cols cg*16 .. cg*16+15
    const int batch = blockIdx.x * 8 + w;
    const int l    = lane;
    const int l2   = lane + 32;

    __shared__ float sGw[256];
    __shared__ float sRed[16];
    __shared__ float sCst[2];                         // Sgw, Sbw
    __shared__ __align__(16) float4 sX[8][2][64];     // per-warp x staging (swizzled)
    __shared__ __align__(16) float  sY[8][2][256];    // per-warp y staging, k-major
    __shared__ float sSA[8][256];   // per-warp: [0:64)=xscale [64:128)=yscale
                                    //           [128:192)=xalpha [192:256)=yalpha

    // ---- prologue constants (only CTA-wide sync in the kernel) ----
    {
        float gwv = gamma[t] * wdb[t];
        float bwv = beta[t] * wdb[t];
        sGw[t] = gwv;
        gwv = warp_sum(gwv);
        bwv = warp_sum(bwv);
        if (lane == 0) { sRed[w] = gwv; sRed[8 + w] = bwv; }
    }
    __syncthreads();
    if (t == 0) {
        float a = 0.f, c = 0.f;
#pragma unroll
        for (int i = 0; i < 8; i++) { a += sRed[i]; c += sRed[8 + i]; }
        sCst[0] = a;
        sCst[1] = c + bdb[0];
    }
    __syncthreads();
    const float Sgw = sCst[0], Sbw = sCst[1];

    const float4* xg  = (const float4*)(x + (size_t)batch * 64 * 256);
    const float4* yg  = (const float4*)(y + (size_t)batch * 64 * 256);
    const float4* gw4 = (const float4*)sGw;

    // ---- GEMM: acc[r][cp] packs cols (cg*16+2cp, +1) for row rg*8+r ----
    unsigned long long acc[8][8];
#pragma unroll
    for (int r = 0; r < 8; r++)
#pragma unroll
        for (int cp = 0; cp < 8; cp++) acc[r][cp] = 0ull;

    float sx1[2] = {0.f, 0.f}, sx2[2] = {0.f, 0.f}, sx3[2] = {0.f, 0.f};
    float sy1[2] = {0.f, 0.f}, sy2[2] = {0.f, 0.f}, sy3[2] = {0.f, 0.f};

    const int xu0 = l ^ (l >> 3);
    const int xu1 = l2 ^ (l2 >> 3);

    float4 px0 = xg[l * 64], px1 = xg[l2 * 64];
    float4 py0 = yg[l * 64], py1 = yg[l2 * 64];

#pragma unroll 1
    for (int kc = 0; kc < 64; kc++) {
        float4* Xb = sX[w][kc & 1];
        float*  Yb = sY[w][kc & 1];
        Xb[xu0] = px0;
        Xb[xu1] = px1;
        Yb[0 * 64 + l]  = py0.x; Yb[1 * 64 + l]  = py0.y;
        Yb[2 * 64 + l]  = py0.z; Yb[3 * 64 + l]  = py0.w;
        Yb[0 * 64 + l2] = py1.x; Yb[1 * 64 + l2] = py1.y;
        Yb[2 * 64 + l2] = py1.z; Yb[3 * 64 + l2] = py1.w;
        // stats (fused)
        {
            float4 gq = gw4[kc];
            sx1[0] += (px0.x + px0.y) + (px0.z + px0.w);
            sx2[0] += px0.x * px0.x + px0.y * px0.y + px0.z * px0.z + px0.w * px0.w;
            sx3[0] += px0.x * gq.x + px0.y * gq.y + px0.z * gq.z + px0.w * gq.w;
            sx1[1] += (px1.x + px1.y) + (px1.z + px1.w);
            sx2[1] += px1.x * px1.x + px1.y * px1.y + px1.z * px1.z + px1.w * px1.w;
            sx3[1] += px1.x * gq.x + px1.y * gq.y + px1.z * gq.z + px1.w * gq.w;
            sy1[0] += (py0.x + py0.y) + (py0.z + py0.w);
            sy2[0] += py0.x * py0.x + py0.y * py0.y + py0.z * py0.z + py0.w * py0.w;
            sy3[0] += py0.x * gq.x + py0.y * gq.y + py0.z * gq.z + py0.w * gq.w;
            sy1[1] += (py1.x + py1.y) + (py1.z + py1.w);
            sy2[1] += py1.x * py1.x + py1.y * py1.y + py1.z * py1.z + py1.w * py1.w;
            sy3[1] += py1.x * gq.x + py1.y * gq.y + py1.z * gq.z + py1.w * gq.w;
        }
        __syncwarp();
        if (kc < 63) {                 // prefetch next chunk
            px0 = xg[l * 64 + kc + 1];
            px1 = xg[l2 * 64 + kc + 1];
            py0 = yg[l * 64 + kc + 1];
            py1 = yg[l2 * 64 + kc + 1];
        }
        const float* Xs = (const float*)Xb;
#pragma unroll
        for (int k = 0; k < 4; k++) {
            const ulonglong2* yk = (const ulonglong2*)(Yb + k * 64 + cg * 16);
            ulonglong2 ya = yk[0], yb2 = yk[1];
#pragma unroll
            for (int r = 0; r < 8; r++) {
                int row = rg * 8 + r;
                float xs = Xs[((row ^ rg) << 2) + k];
                unsigned long long xx = pack2(xs, xs);
                acc[r][0] = ffma2(xx, ya.x,  acc[r][0]);
                acc[r][1] = ffma2(xx, ya.y,  acc[r][1]);
                acc[r][2] = ffma2(xx, yb2.x, acc[r][2]);
                acc[r][3] = ffma2(xx, yb2.y, acc[r][3]);
            }
            const ulonglong2* yk2 = yk + 2;
            ulonglong2 yc = yk2[0], yd = yk2[1];
#pragma unroll
            for (int r = 0; r < 8; r++) {
                int row = rg * 8 + r;
                float xs = Xs[((row ^ rg) << 2) + k];
                unsigned long long xx = pack2(xs, xs);
                acc[r][4] = ffma2(xx, yc.x, acc[r][4]);
                acc[r][5] = ffma2(xx, yc.y, acc[r][5]);
                acc[r][6] = ffma2(xx, yd.x, acc[r][6]);
                acc[r][7] = ffma2(xx, yd.y, acc[r][7]);
            }
        }
        __syncwarp();
    }

    // ---- stats finalize: lane owns x rows l, l2 and y rows l, l2 ----
    {
        float* SA = sSA[w];
#pragma unroll
        for (int q = 0; q < 2; q++) {
            int row = (q == 0) ? l : l2;
            SA[row] = 1.0f / fmaxf(sqrtf(sx2[q]), 1e-12f);
            float mu  = sx1[q] * (1.0f / 256.0f);
            float var = sx2[q] * (1.0f / 256.0f) - mu * mu;
            SA[128 + row] = tanhf(rsqrtf(var + 1e-5f) * (sx3[q] - mu * Sgw) + Sbw);
            SA[64 + row] = 1.0f / fmaxf(sqrtf(sy2[q]), 1e-12f);
            float muy  = sy1[q] * (1.0f / 256.0f);
            float vary = sy2[q] * (1.0f / 256.0f) - muy * muy;
            SA[192 + row] = tanhf(rsqrtf(vary + 1e-5f) * (sy3[q] - muy * Sgw) + Sbw);
        }
    }
    __syncwarp();

    // ---- C scaling + K = exp(C) in registers ----
    unsigned long long kreg[8][8];
    {
        const float* SA = sSA[w];
        float sj10[16];
#pragma unroll
        for (int c = 0; c < 16; c++) sj10[c] = SA[64 + cg * 16 + c] * 10.0f;
#pragma unroll
        for (int r = 0; r < 8; r++) {
            float si = SA[rg * 8 + r];
#pragma unroll
            for (int cp = 0; cp < 8; cp++) {
                float c0, c1;
                unpack2(acc[r][cp], c0, c1);
                c0 *= si * sj10[2 * cp];
                c1 *= si * sj10[2 * cp + 1];
                kreg[r][cp] = pack2(__expf(c0), __expf(c1));
            }
        }
    }
    // dustbin kernels
    float kcol64[8];                 // K[row][64] = exp(10*alpha_x[row])
    unsigned long long kdrow[8];     // K[64][col pair] = exp(10*alpha_y[col])
    {
        const float* SA = sSA[w];
#pragma unroll
        for (int r = 0; r < 8; r++)
            kcol64[r] = __expf(10.0f * SA[128 + rg * 8 + r]);
#pragma unroll
        for (int cp = 0; cp < 8; cp++)
            kdrow[cp] = pack2(__expf(10.0f * SA[192 + cg * 16 + 2 * cp]),
                              __expf(10.0f * SA[192 + cg * 16 + 2 * cp + 1]));
    }

    // ---- Sinkhorn: 20 iterations, fully warp-local ----
    unsigned long long b2[8];
#pragma unroll
    for (int cp = 0; cp < 8; cp++) b2[cp] = pack2(1.f, 1.f);
    float b64 = 1.f, a64 = 0.f;
    float a[8];
    const bool own_db = (rg == 0);   // dustbin-row term seeded exactly once

#pragma unroll 1
    for (int it = 0; it < 20; it++) {
        // u-phase: row sums over own 16 cols, reduce across cg (xor 1,2)
        float z[8];
#pragma unroll
        for (int r = 0; r < 8; r++) {
            unsigned long long s = fmul2(kreg[r][0], b2[0]);
#pragma unroll
            for (int cp = 1; cp < 8; cp++) s = ffma2(kreg[r][cp], b2[cp], s);
            z[r] = pairsum(s);
        }
#pragma unroll
        for (int r = 0; r < 8; r++) {
            z[r] += __shfl_xor_sync(0xffffffffu, z[r], 1);
            z[r] += __shfl_xor_sync(0xffffffffu, z[r], 2);
        }
        // dustbin row sum -> a64 (cols distinct within cg group -> correct)
        {
            unsigned long long s = fmul2(kdrow[0], b2[0]);
#pragma unroll
            for (int cp = 1; cp < 8; cp++) s = ffma2(kdrow[cp], b2[cp], s);
            float zz = pairsum(s);
            zz += __shfl_xor_sync(0xffffffffu, zz, 1);
            zz += __shfl_xor_sync(0xffffffffu, zz, 2);
            a64 = __fdividef(MU_DB, zz);
        }
#pragma unroll
        for (int r = 0; r < 8; r++)
            a[r] = __fdividef(MU_IN, fmaf(kcol64[r], b64, z[r]));

        // v-phase: col sums over own 8 rows (+ dustbin row ONCE), reduce rg
        unsigned long long q[8];
        {
            unsigned long long a642 = own_db ? pack2(a64, a64) : 0ull;
#pragma unroll
            for (int cp = 0; cp < 8; cp++)
                q[cp] = own_db ? fmul2(kdrow[cp], a642) : 0ull;
        }
        float zb = 0.f;
#pragma unroll
        for (int r = 0; r < 8; r++) {
            unsigned long long a2r = pack2(a[r], a[r]);
#pragma unroll
            for (int cp = 0; cp < 8; cp++) q[cp] = ffma2(kreg[r][cp], a2r, q[cp]);
            zb = fmaf(kcol64[r], a[r], zb);
        }
#pragma unroll
        for (int off = 4; off <= 16; off <<= 1) {
#pragma unroll
            for (int cp = 0; cp < 8; cp++)
                q[cp] = fadd2(q[cp], __shfl_xor_sync(0xffffffffu, q[cp], off));
            zb += __shfl_xor_sync(0xffffffffu, zb, off);
        }
#pragma unroll
        for (int cp = 0; cp < 8; cp++) {
            float q0, q1;
            unpack2(q[cp], q0, q1);
            b2[cp] = pack2(__fdividef(MU_IN, q0), __fdividef(MU_IN, q1));
        }
        b64 = __fdividef(MU_DB, zb);
    }

    // ---- epilogue: matching (C = __logf(K)) + score ----
    float lb[16];
#pragma unroll
    for (int cp = 0; cp < 8; cp++) {
        float q0, q1;
        unpack2(b2[cp], q0, q1);
        lb[2 * cp]     = __logf(q0);
        lb[2 * cp + 1] = __logf(q1);
    }
    float la64  = __logf(a64);
    float lb64l = __logf(b64);
    float* om = out_match + (size_t)batch * (NP * NP);
    float p = 0.f;
    const float* SA = sSA[w];
#pragma unroll
    for (int r = 0; r < 8; r++) {
        int row = rg * 8 + r;
        float laf = __logf(a[r]) + LOG128;
        float* orow = om + row * NP + cg * 16;
#pragma unroll
        for (int cp = 0; cp < 8; cp++) {
            float k0, k1, bb0, bb1;
            unpack2(kreg[r][cp], k0, k1);
            unpack2(b2[cp], bb0, bb1);
            float c0 = __logf(k0);
            float c1 = __logf(k1);
            orow[2 * cp]     = c0 + laf + lb[2 * cp];
            orow[2 * cp + 1] = c1 + laf + lb[2 * cp + 1];
            p += a[r] * (k0 * c0 * bb0 + k1 * c1 * bb1);
        }
        if (cg == 0)
            om[row * NP + 64] = 10.0f * SA[128 + row] + laf + lb64l;
    }
    if (rg == 0) {
#pragma unroll
        for (int c = 0; c < 16; c++) {
            int col = cg * 16 + c;
            om[64 * NP + col] = 10.0f * SA[192 + col] + la64 + LOG128 + lb[c];
        }
    }
    if (lane == 0)
        om[64 * NP + 64] = -1000.0f + la64 + lb64l + LOG128;

    if (write_score) {
        p = warp_sum(p);
        if (lane == 0) out_score[batch] = p * 128.0f;
    }
}

extern "C" void kernel_launch(void* const* d_in, const int* in_sizes, int n_in,
                              void* d_out, int out_size) {
    const float* x     = (const float*)d_in[0];
    const float* y     = (const float*)d_in[1];
    const float* gamma = (const float*)d_in[2];
    const float* beta  = (const float*)d_in[3];
    const float* wdb   = (const float*)d_in[4];
    const float* bdb   = (const float*)d_in[5];

    int B = in_sizes[0] / (64 * 256);               // 4096 (multiple of 8)
    size_t msz = (size_t)B * NP * NP;
    float* out_match = (float*)d_out;
    float* out_score = (float*)d_out + msz;
    int write_score = ((size_t)out_size >= msz + (size_t)B) ? 1 : 0;

    sinkhorn_fused_kernel<<<B / 8, 256>>>(x, y, gamma, beta, wdb, bdb,
                                          out_match, out_score, write_score);
}